// round 11
// baseline (speedup 1.0000x reference)
#include <cuda_runtime.h>
#include <cstdint>

// RWKV v4 single-token forward, persistent kernel, round 11.
// Warp-specialized HYBRID streaming. Warps 0-15: direct LDG.128 dots (engine
// capped at the per-SM LDG issue floor, ~2.4TB/s chip). Warps 16-31: TMA
// engine -- per-warp double-buffered 4KB smem slots + private mbarriers,
// consuming the second half of each stage's rows; next-stage tiles issued
// BEFORE each grid barrier. R10's bug (TMA rows indexed past the task count,
// so TMA never fired: tma=0.1%) is fixed by a static 50/50 pool split.
// Param staging (single-buffer, prefetch after last use) restored from R5.

#define E    1024
#define HH   4096
#define NL   24
#define NV   50277
#define T    1024
#define WPB  32
#define NLW  16              // LDG-engine warps per block
#define NTW  16              // TMA-engine warps per block
#define NPAR 16

// ---- persistent device scratch ----
__device__ float g_kvr[3 * E];
__device__ float g_ow[E];
__device__ float g_fk[HH];
__device__ float g_fr[E];
__device__ __align__(16) float g_fvd[4 * E];
__device__ unsigned int g_bar[2];   // memset per launch

struct P {
    const float *ctx, *state, *ln0w, *ln0b, *ln1w, *ln1b, *ln2w, *ln2b;
    const float *td, *tf, *tmk, *tmv, *tmr, *kw, *vw, *rw, *ow;
    const float *ftmk, *ftmr, *fkw, *frw, *fvw, *lnoutw, *lnoutb, *head;
    float* out;
    int nb;
    int ws;
};

__device__ __forceinline__ void grid_sync(int nb) {
    __syncthreads();
    if (threadIdx.x == 0) {
        unsigned int gen = ((volatile unsigned int*)g_bar)[1];
        __threadfence();
        if (atomicAdd(&g_bar[0], 1u) == (unsigned int)(nb - 1)) {
            atomicExch(&g_bar[0], 0u);
            __threadfence();
            atomicAdd(&g_bar[1], 1u);
        } else {
            while (((volatile unsigned int*)g_bar)[1] == gen) { __nanosleep(64); }
        }
        __threadfence();
    }
    __syncthreads();
}

__device__ __forceinline__ void block_reduce2(float& a, float& b, float* sr) {
    #pragma unroll
    for (int o = 16; o; o >>= 1) {
        a += __shfl_down_sync(0xFFFFFFFFu, a, o);
        b += __shfl_down_sync(0xFFFFFFFFu, b, o);
    }
    int w = threadIdx.x >> 5, l = threadIdx.x & 31;
    __syncthreads();
    if (l == 0) { sr[w] = a; sr[w + WPB] = b; }
    __syncthreads();
    if (threadIdx.x == 0) {
        float sa = 0.f, sb2 = 0.f;
        #pragma unroll
        for (int i = 0; i < WPB; i++) { sa += sr[i]; sb2 += sr[i + WPB]; }
        sr[2 * WPB] = sa; sr[2 * WPB + 1] = sb2;
    }
    __syncthreads();
    a = sr[2 * WPB];
    b = sr[2 * WPB + 1];
}

// global-memory warp dot over 1024 floats (.cs read-once)
__device__ __forceinline__ float dot_g(const float* __restrict__ w,
                                       const float* x, int lane) {
    const float4* __restrict__ w4 = (const float4*)w;
    const float4* x4 = (const float4*)x;
    float a0 = 0.f, a1 = 0.f, a2 = 0.f, a3 = 0.f;
    #pragma unroll
    for (int u = 0; u < 8; u += 4) {
        float4 wa = __ldcs(&w4[lane + 32 * u]);       float4 xa = x4[lane + 32 * u];
        float4 wb = __ldcs(&w4[lane + 32 * (u + 1)]); float4 xb = x4[lane + 32 * (u + 1)];
        float4 wc = __ldcs(&w4[lane + 32 * (u + 2)]); float4 xc = x4[lane + 32 * (u + 2)];
        float4 wd = __ldcs(&w4[lane + 32 * (u + 3)]); float4 xd = x4[lane + 32 * (u + 3)];
        a0 += wa.x * xa.x + wa.y * xa.y + wa.z * xa.z + wa.w * xa.w;
        a1 += wb.x * xb.x + wb.y * xb.y + wb.z * xb.z + wb.w * xb.w;
        a2 += wc.x * xc.x + wc.y * xc.y + wc.z * xc.z + wc.w * xc.w;
        a3 += wd.x * xd.x + wd.y * xd.y + wd.z * xd.z + wd.w * xd.w;
    }
    float acc = (a0 + a1) + (a2 + a3);
    #pragma unroll
    for (int o = 16; o; o >>= 1) acc += __shfl_down_sync(0xFFFFFFFFu, acc, o);
    return acc;
}

// smem-slot warp dot over 1024 floats
__device__ __forceinline__ float dot_s(const float* w, const float* x, int lane) {
    const float4* w4 = (const float4*)w;
    const float4* x4 = (const float4*)x;
    float a0 = 0.f, a1 = 0.f, a2 = 0.f, a3 = 0.f;
    #pragma unroll
    for (int u = 0; u < 8; u += 4) {
        float4 wa = w4[lane + 32 * u];       float4 xa = x4[lane + 32 * u];
        float4 wb = w4[lane + 32 * (u + 1)]; float4 xb = x4[lane + 32 * (u + 1)];
        float4 wc = w4[lane + 32 * (u + 2)]; float4 xc = x4[lane + 32 * (u + 2)];
        float4 wd = w4[lane + 32 * (u + 3)]; float4 xd = x4[lane + 32 * (u + 3)];
        a0 += wa.x * xa.x + wa.y * xa.y + wa.z * xa.z + wa.w * xa.w;
        a1 += wb.x * xb.x + wb.y * xb.y + wb.z * xb.z + wb.w * xb.w;
        a2 += wc.x * xc.x + wc.y * xc.y + wc.z * xc.z + wc.w * xc.w;
        a3 += wd.x * xd.x + wd.y * xd.y + wd.z * xd.z + wd.w * xd.w;
    }
    float acc = (a0 + a1) + (a2 + a3);
    #pragma unroll
    for (int o = 16; o; o >>= 1) acc += __shfl_down_sync(0xFFFFFFFFu, acc, o);
    return acc;
}

// ---- mbarrier / bulk-copy primitives ----
__device__ __forceinline__ void mb_init(uint32_t a, uint32_t cnt) {
    asm volatile("mbarrier.init.shared.b64 [%0], %1;" :: "r"(a), "r"(cnt) : "memory");
}
__device__ __forceinline__ void mb_expect(uint32_t a, uint32_t tx) {
    asm volatile("mbarrier.arrive.expect_tx.shared.b64 _, [%0], %1;" :: "r"(a), "r"(tx) : "memory");
}
__device__ __forceinline__ void mb_wait(uint32_t a, uint32_t parity) {
    uint32_t done;
    asm volatile(
        "{\n\t.reg .pred p;\n\t"
        "mbarrier.try_wait.parity.acquire.cta.shared::cta.b64 p, [%1], %2;\n\t"
        "selp.b32 %0, 1, 0, p;\n\t}"
        : "=r"(done) : "r"(a), "r"(parity) : "memory");
    if (!done) {
        asm volatile(
            "{\n\t.reg .pred P1;\n\t"
            "WAIT_LOOP_%=:\n\t"
            "mbarrier.try_wait.parity.acquire.cta.shared::cta.b64 P1, [%0], %1, 0x989680;\n\t"
            "@P1 bra.uni WAIT_DONE_%=;\n\t"
            "bra.uni WAIT_LOOP_%=;\n\t"
            "WAIT_DONE_%=:\n\t}"
            :: "r"(a), "r"(parity) : "memory");
    }
}
__device__ __forceinline__ void bulk_ld(uint32_t dst, const float* src, uint32_t bytes, uint32_t mbar) {
    asm volatile(
        "cp.async.bulk.shared::cluster.global.mbarrier::complete_tx::bytes [%0], [%1], %2, [%3];"
        :: "r"(dst), "l"(src), "r"(bytes), "r"(mbar) : "memory");
}

// ---- virtual-row mapping: every task is one 4KB row ----
__device__ __forceinline__ const float* srcptr(const P& p, int stg, int l, int vr) {
    switch (stg) {
        case 0: { int m = vr >> 10;
                  const float* W = (m == 0 ? p.kw : (m == 1 ? p.vw : p.rw)) + (size_t)l * E * E;
                  return W + (size_t)(vr & 1023) * E; }
        case 1: return p.ow + (size_t)l * E * E + (size_t)vr * E;
        case 2: return (vr < 4096) ? p.fkw + (size_t)l * HH * E + (size_t)vr * E
                                   : p.frw + (size_t)l * E * E + (size_t)(vr - 4096) * E;
        case 3: return p.fvw + (size_t)l * E * HH + (size_t)vr * E;
        default: return p.head + (size_t)vr * E;
    }
}
__device__ __forceinline__ int xoff(int stg, int vr) {
    switch (stg) {
        case 0: return (vr >> 10) << 10;
        case 2: return (vr < 4096) ? 0 : E;
        case 3: return (vr & 3) << 10;
        default: return 0;
    }
}
__device__ __forceinline__ float* outp(const P& p, int stg, int vr) {
    switch (stg) {
        case 0: return g_kvr + vr;
        case 1: return g_ow + vr;
        case 2: return (vr < 4096) ? g_fk + vr : g_fr + (vr - 4096);
        case 3: return g_fvd + vr;
        default: return p.out + vr;
    }
}
__device__ __forceinline__ int stageNT(int stg) {
    switch (stg) {
        case 0: return 3 * E;
        case 1: return E;
        case 2: return HH + E;
        case 3: return 4 * E;
        default: return NV;
    }
}

// ---- TMA engine state (per TMA warp) ----
struct TQ {
    int ti, tc, end, stride, stg, l;
    int ic, cc;      // global issue/consume counters (slot = ctr & 1)
    int ph[2];       // per-slot parity
};

__device__ __forceinline__ void tq_issue(TQ& q, const P& p, uint32_t slots_u32,
                                         uint32_t mybar, int lane) {
    if (q.ti >= q.end) return;
    int s = q.ic & 1;
    if (lane == 0) {
        mb_expect(mybar + s * 8, 4096u);
        bulk_ld(slots_u32 + (uint32_t)s * 4096u, srcptr(p, q.stg, q.l, q.ti), 4096u, mybar + s * 8);
    }
    q.ic++;
    q.ti += q.stride;
}

// begin a stage: TMA pool = rows [NT/2, NT)
__device__ __forceinline__ void tq_begin(TQ& q, int stg, int l, const P& p,
                                         uint32_t slots_u32, uint32_t mybar,
                                         int lane, int gwT, int NWT) {
    int NT = stageNT(stg);
    int half = NT >> 1;
    q.stg = stg; q.l = l;
    q.ti = half + gwT;
    q.tc = q.ti;
    q.end = NT;
    q.stride = NWT;
    tq_issue(q, p, slots_u32, mybar, lane);
    tq_issue(q, p, slots_u32, mybar, lane);
}

__device__ __forceinline__ void tq_drain(TQ& q, const P& p, float* slots, float* sop,
                                         uint32_t slots_u32, uint32_t mybar, int lane) {
    while (q.tc < q.end) {
        int s = q.cc & 1;
        mb_wait(mybar + s * 8, (uint32_t)q.ph[s]);
        q.ph[s] ^= 1;
        q.cc++;
        float acc = dot_s(slots + s * E, sop + xoff(q.stg, q.tc), lane);
        if (lane == 0) *outp(p, q.stg, q.tc) = acc;
        q.tc += q.stride;
        __syncwarp();
        tq_issue(q, p, slots_u32, mybar, lane);   // refill freed slot (alternation holds)
    }
}

// LDG engine: pool = rows [0, NT/2)
__device__ __forceinline__ void ldg_run(int stg, int l, const P& p, float* sop,
                                        int lane, int gwL, int NWL) {
    int half = stageNT(stg) >> 1;
    for (int t = gwL; t < half; t += NWL) {
        float acc = dot_g(srcptr(p, stg, l, t), sop + xoff(stg, t), lane);
        if (lane == 0) *outp(p, stg, t) = acc;
    }
}

// ---- param staging (single buffer; prefetched after last use in stage C) ----
__device__ __forceinline__ void cpa16(float* smem_dst, const float* g) {
    unsigned saddr = (unsigned)__cvta_generic_to_shared(smem_dst);
    asm volatile("cp.async.cg.shared.global [%0], [%1], 16;" :: "r"(saddr), "l"(g));
}
__device__ __forceinline__ const float* par_src(const P& p, int l, int a) {
    const float* st = p.state + (size_t)l * 5 * E;
    switch (a) {
        case 0:  return p.ln1w + l * E;
        case 1:  return p.ln1b + l * E;
        case 2:  return p.tmk + l * E;
        case 3:  return p.tmv + l * E;
        case 4:  return p.tmr + l * E;
        case 5:  return st + E;
        case 6:  return p.tf + l * E;
        case 7:  return p.td + l * E;
        case 8:  return st + 2 * E;
        case 9:  return st + 3 * E;
        case 10: return st + 4 * E;
        case 11: return p.ln2w + l * E;
        case 12: return p.ln2b + l * E;
        case 13: return p.ftmk + l * E;
        case 14: return p.ftmr + l * E;
        default: return st;
    }
}
__device__ __forceinline__ void prefetch_layer(const P& p, int l1, float* dst) {
    if (l1 < NL) {
        for (int t = threadIdx.x; t < NPAR * 256; t += T) {
            int a = t >> 8, i = (t & 255) << 2;
            cpa16(dst + a * E + i, par_src(p, l1, a) + i);
        }
    } else if (l1 == NL) {
        for (int t = threadIdx.x; t < 512; t += T) {
            int a = t >> 8, i = (t & 255) << 2;
            cpa16(dst + a * E + i, (a ? p.lnoutb : p.lnoutw) + i);
        }
    }
    asm volatile("cp.async.commit_group;" ::: "memory");
}
#define CP_WAIT() asm volatile("cp.async.wait_group 0;" ::: "memory")

// smem: sx[E] + sop[HH] + par[NPAR*E] + slots[NTW*2*E]
#define SMEM_FLOATS (E + HH + NPAR * E + NTW * 2 * E)

__global__ void __launch_bounds__(T, 1) rwkv_kernel(P p) {
    extern __shared__ float smem[];
    float* sx    = smem;                       // [E]
    float* sop   = smem + E;                   // [HH]
    float* par   = smem + E + HH;              // [NPAR*E]
    float* slots = smem + E + HH + NPAR * E;   // [NTW*2*E]
    __shared__ float sred[2 * WPB + 2];
    __shared__ __align__(8) uint64_t mbars[NTW * 2];

    const int tid = threadIdx.x, lane = tid & 31, warp = tid >> 5;
    const bool isT = (warp >= NLW);
    const int gwL = blockIdx.x * NLW + warp;               // valid if !isT
    const int gwT = blockIdx.x * NTW + (warp - NLW);       // valid if isT
    const int NWL = p.nb * NLW;
    const int NWT = p.nb * NTW;
    const bool w0 = (p.ws && blockIdx.x == 0);
    float* outS = p.out + NV;

    float* myslots = slots + (warp - NLW) * 2 * E;         // 2 x 4KB
    uint32_t mybar = 0, slots_u32 = 0;
    if (isT) {
        asm("{ .reg .u64 t; cvta.to.shared.u64 t, %1; cvt.u32.u64 %0, t; }"
            : "=r"(mybar) : "l"((void*)&mbars[(warp - NLW) * 2]));
        asm("{ .reg .u64 t; cvta.to.shared.u64 t, %1; cvt.u32.u64 %0, t; }"
            : "=r"(slots_u32) : "l"((void*)myslots));
        if (lane == 0) { mb_init(mybar, 1); mb_init(mybar + 8, 1); }
    }
    __syncthreads();

    TQ q; q.ic = 0; q.cc = 0; q.ph[0] = 0; q.ph[1] = 0;
    q.tc = 0; q.end = 0; q.ti = 0; q.stride = 1; q.stg = 0; q.l = 0;

    prefetch_layer(p, 0, par);
    if (isT) tq_begin(q, 0, 0, p, slots_u32, mybar, lane, gwT, NWT);

    float s = 0.f, s2 = 0.f;
    for (int i = tid; i < E; i += T) { float v = __ldg(p.ctx + i); sx[i] = v; s += v; s2 += v * v; }
    block_reduce2(s, s2, sred);
    {
        float mu = s * (1.f / E);
        float rs = rsqrtf(s2 * (1.f / E) - mu * mu + 1e-5f);
        for (int i = tid; i < E; i += T)
            sx[i] = (sx[i] - mu) * rs * __ldg(p.ln0w + i) + __ldg(p.ln0b + i);
    }
    CP_WAIT();
    __syncthreads();

    for (int l = 0; l < NL; l++) {
        // ======== Stage A: combine prev FFN + LN1 + time-mix; kvr GEMV ========
        if (l > 0) {
            for (int i = tid; i < E; i += T) {
                float4 fv4 = *(const float4*)(g_fvd + 4 * i);
                float fr = 1.f / (1.f + __expf(-g_fr[i]));
                sx[i] += fr * ((fv4.x + fv4.y) + (fv4.z + fv4.w));
            }
        }
        s = 0.f; s2 = 0.f;
        for (int i = tid; i < E; i += T) { float v = sx[i]; s += v; s2 += v * v; }
        block_reduce2(s, s2, sred);
        {
            float mu = s * (1.f / E);
            float rs = rsqrtf(s2 * (1.f / E) - mu * mu + 1e-5f);
            for (int i = tid; i < E; i += T) {
                float xn = (sx[i] - mu) * rs * par[0 * E + i] + par[1 * E + i];
                float spv = par[5 * E + i];
                float a = par[2 * E + i], b = par[3 * E + i], c = par[4 * E + i];
                sop[i]         = xn * a + spv * (1.f - a);
                sop[E + i]     = xn * b + spv * (1.f - b);
                sop[2 * E + i] = xn * c + spv * (1.f - c);
                if (w0) outS[(size_t)(5 * l + 1) * E + i] = xn;
            }
        }
        __syncthreads();
        if (isT) { tq_drain(q, p, myslots, sop, slots_u32, mybar, lane);
                   tq_begin(q, 1, l, p, slots_u32, mybar, lane, gwT, NWT); }
        else     ldg_run(0, l, p, sop, lane, gwL, NWL);
        grid_sync(p.nb);

        // ======== Stage B: WKV; ow GEMV ========
        for (int i = tid; i < E; i += T) {
            float k  = g_kvr[i];
            float v  = g_kvr[E + i];
            float rr = g_kvr[2 * E + i];
            float A = par[8 * E + i], B = par[9 * E + i], Pp = par[10 * E + i];
            float ww = par[6 * E + i] + k;
            float qq = fmaxf(Pp, ww);
            float e1 = __expf(Pp - qq), e2 = __expf(ww - qq);
            float num = e1 * A + e2 * v, den = e1 * B + e2;
            float r = 1.f / (1.f + __expf(-rr));
            sop[i] = r * num / den;
            if (w0) {
                float ww2 = Pp + par[7 * E + i];
                float p2 = fmaxf(ww2, k);
                float e1b = __expf(ww2 - p2), e2b = __expf(k - p2);
                outS[(size_t)(5 * l + 2) * E + i] = e1b * A + e2b * v;
                outS[(size_t)(5 * l + 3) * E + i] = e1b * B + e2b;
                outS[(size_t)(5 * l + 4) * E + i] = p2;
            }
        }
        __syncthreads();
        if (isT) { tq_drain(q, p, myslots, sop, slots_u32, mybar, lane);
                   tq_begin(q, 2, l, p, slots_u32, mybar, lane, gwT, NWT); }
        else     ldg_run(1, l, p, sop, lane, gwL, NWL);
        grid_sync(p.nb);

        // ======== Stage C: x += ow; LN2 + chan-mix; fk+fr GEMV ========
        for (int i = tid; i < E; i += T) sx[i] += g_ow[i];
        s = 0.f; s2 = 0.f;
        for (int i = tid; i < E; i += T) { float v = sx[i]; s += v; s2 += v * v; }
        block_reduce2(s, s2, sred);
        {
            float mu = s * (1.f / E);
            float rs = rsqrtf(s2 * (1.f / E) - mu * mu + 1e-5f);
            for (int i = tid; i < E; i += T) {
                float xn2 = (sx[i] - mu) * rs * par[11 * E + i] + par[12 * E + i];
                float sv = par[15 * E + i];
                float a = par[13 * E + i], b = par[14 * E + i];
                sop[i]     = xn2 * a + sv * (1.f - a);
                sop[E + i] = xn2 * b + sv * (1.f - b);
                if (w0) outS[(size_t)(5 * l + 0) * E + i] = xn2;
            }
        }
        __syncthreads();
        prefetch_layer(p, l + 1, par);   // params' last use was just above
        if (isT) { tq_drain(q, p, myslots, sop, slots_u32, mybar, lane);
                   tq_begin(q, 3, l, p, slots_u32, mybar, lane, gwT, NWT); }
        else     ldg_run(2, l, p, sop, lane, gwL, NWL);
        grid_sync(p.nb);

        // ======== Stage D: kk = relu^2(fk); fv GEMV ========
        for (int i = tid; i < HH; i += T) {
            float a = fmaxf(g_fk[i], 0.f);
            sop[i] = a * a;
        }
        __syncthreads();
        if (isT) { tq_drain(q, p, myslots, sop, slots_u32, mybar, lane);
                   tq_begin(q, (l + 1 < NL) ? 0 : 4, (l + 1 < NL) ? l + 1 : 0,
                            p, slots_u32, mybar, lane, gwT, NWT); }
        else     ldg_run(3, l, p, sop, lane, gwL, NWL);
        grid_sync(p.nb);
        CP_WAIT();
    }

    // ======== final: combine last FFN, LN_out, head GEMV ========
    for (int i = tid; i < E; i += T) {
        float4 fv4 = *(const float4*)(g_fvd + 4 * i);
        float fr = 1.f / (1.f + __expf(-g_fr[i]));
        sx[i] += fr * ((fv4.x + fv4.y) + (fv4.z + fv4.w));
    }
    s = 0.f; s2 = 0.f;
    for (int i = tid; i < E; i += T) { float v = sx[i]; s += v; s2 += v * v; }
    block_reduce2(s, s2, sred);
    {
        float mu = s * (1.f / E);
        float rs = rsqrtf(s2 * (1.f / E) - mu * mu + 1e-5f);
        for (int i = tid; i < E; i += T)
            sop[i] = (sx[i] - mu) * rs * par[i] + par[E + i];
    }
    __syncthreads();
    if (isT) tq_drain(q, p, myslots, sop, slots_u32, mybar, lane);
    else     ldg_run(4, 0, p, sop, lane, gwL, NWL);
}

extern "C" void kernel_launch(void* const* d_in, const int* in_sizes, int n_in,
                              void* d_out, int out_size) {
    (void)in_sizes; (void)n_in;
    P p;
    p.ctx    = (const float*)d_in[0];
    p.state  = (const float*)d_in[1];
    p.ln0w   = (const float*)d_in[2];
    p.ln0b   = (const float*)d_in[3];
    p.ln1w   = (const float*)d_in[4];
    p.ln1b   = (const float*)d_in[5];
    p.ln2w   = (const float*)d_in[6];
    p.ln2b   = (const float*)d_in[7];
    p.td     = (const float*)d_in[8];
    p.tf     = (const float*)d_in[9];
    p.tmk    = (const float*)d_in[10];
    p.tmv    = (const float*)d_in[11];
    p.tmr    = (const float*)d_in[12];
    p.kw     = (const float*)d_in[13];
    p.vw     = (const float*)d_in[14];
    p.rw     = (const float*)d_in[15];
    p.ow     = (const float*)d_in[16];
    p.ftmk   = (const float*)d_in[17];
    p.ftmr   = (const float*)d_in[18];
    p.fkw    = (const float*)d_in[19];
    p.frw    = (const float*)d_in[20];
    p.fvw    = (const float*)d_in[21];
    p.lnoutw = (const float*)d_in[22];
    p.lnoutb = (const float*)d_in[23];
    p.head   = (const float*)d_in[24];
    p.out    = (float*)d_out;

    int dev = 0;
    cudaGetDevice(&dev);
    int nsm = 0;
    cudaDeviceGetAttribute(&nsm, cudaDevAttrMultiProcessorCount, dev);
    if (nsm <= 0) nsm = 148;
    if (nsm > 256) nsm = 256;
    p.nb = nsm;
    p.ws = (out_size >= NV + 5 * NL * E) ? 1 : 0;

    cudaFuncSetAttribute(rwkv_kernel, cudaFuncAttributeMaxDynamicSharedMemorySize,
                         SMEM_FLOATS * sizeof(float));

    void* baddr = nullptr;
    cudaGetSymbolAddress(&baddr, g_bar);
    cudaMemsetAsync(baddr, 0, sizeof(unsigned int) * 2, 0);

    rwkv_kernel<<<nsm, T, SMEM_FLOATS * sizeof(float)>>>(p);
}

// round 12
// speedup vs baseline: 1.0359x; 1.0359x over previous
#include <cuda_runtime.h>
#include <cstdint>

// RWKV v4 single-token forward, persistent kernel, round 12.
// Hybrid LDG + TMA with TMA latency fully hidden: per stage each block owns a
// contiguous row range; first q=min(32,n/2) rows are loaded by TMA (one 4KB
// row per warp into a private smem slot, ISSUED ONE STAGE EARLY, before the
// grid barrier), remaining rows are LDG dots shared by all 32 warps. Consume
// of the TMA row hits the mbarrier fast path (data arrived during barrier +
// elementwise + LDG work). R11 failed because transfers were issued JIT
// (serial 600cyc latency per 4KB, ~2.8 B/cyc/SM); this queues them early.

#define E    1024
#define HH   4096
#define NL   24
#define NV   50277
#define T    1024
#define WPB  32
#define NPAR 16

// ---- persistent device scratch ----
__device__ float g_kvr[3 * E];
__device__ float g_ow[E];
__device__ float g_fk[HH];
__device__ float g_fr[E];
__device__ __align__(16) float g_fvd[4 * E];
__device__ unsigned int g_bar[2];   // memset per launch

struct P {
    const float *ctx, *state, *ln0w, *ln0b, *ln1w, *ln1b, *ln2w, *ln2b;
    const float *td, *tf, *tmk, *tmv, *tmr, *kw, *vw, *rw, *ow;
    const float *ftmk, *ftmr, *fkw, *frw, *fvw, *lnoutw, *lnoutb, *head;
    float* out;
    int nb;
    int ws;
};

__device__ __forceinline__ void grid_sync(int nb) {
    __syncthreads();
    if (threadIdx.x == 0) {
        unsigned int gen = ((volatile unsigned int*)g_bar)[1];
        __threadfence();
        if (atomicAdd(&g_bar[0], 1u) == (unsigned int)(nb - 1)) {
            atomicExch(&g_bar[0], 0u);
            __threadfence();
            atomicAdd(&g_bar[1], 1u);
        } else {
            while (((volatile unsigned int*)g_bar)[1] == gen) { __nanosleep(64); }
        }
        __threadfence();
    }
    __syncthreads();
}

__device__ __forceinline__ void block_reduce2(float& a, float& b, float* sr) {
    #pragma unroll
    for (int o = 16; o; o >>= 1) {
        a += __shfl_down_sync(0xFFFFFFFFu, a, o);
        b += __shfl_down_sync(0xFFFFFFFFu, b, o);
    }
    int w = threadIdx.x >> 5, l = threadIdx.x & 31;
    __syncthreads();
    if (l == 0) { sr[w] = a; sr[w + WPB] = b; }
    __syncthreads();
    if (threadIdx.x == 0) {
        float sa = 0.f, sb2 = 0.f;
        #pragma unroll
        for (int i = 0; i < WPB; i++) { sa += sr[i]; sb2 += sr[i + WPB]; }
        sr[2 * WPB] = sa; sr[2 * WPB + 1] = sb2;
    }
    __syncthreads();
    a = sr[2 * WPB];
    b = sr[2 * WPB + 1];
}

// global-memory warp dot over 1024 floats (.cs read-once)
__device__ __forceinline__ float dot_g(const float* __restrict__ w,
                                       const float* x, int lane) {
    const float4* __restrict__ w4 = (const float4*)w;
    const float4* x4 = (const float4*)x;
    float a0 = 0.f, a1 = 0.f, a2 = 0.f, a3 = 0.f;
    #pragma unroll
    for (int u = 0; u < 8; u += 4) {
        float4 wa = __ldcs(&w4[lane + 32 * u]);       float4 xa = x4[lane + 32 * u];
        float4 wb = __ldcs(&w4[lane + 32 * (u + 1)]); float4 xb = x4[lane + 32 * (u + 1)];
        float4 wc = __ldcs(&w4[lane + 32 * (u + 2)]); float4 xc = x4[lane + 32 * (u + 2)];
        float4 wd = __ldcs(&w4[lane + 32 * (u + 3)]); float4 xd = x4[lane + 32 * (u + 3)];
        a0 += wa.x * xa.x + wa.y * xa.y + wa.z * xa.z + wa.w * xa.w;
        a1 += wb.x * xb.x + wb.y * xb.y + wb.z * xb.z + wb.w * xb.w;
        a2 += wc.x * xc.x + wc.y * xc.y + wc.z * xc.z + wc.w * xc.w;
        a3 += wd.x * xd.x + wd.y * xd.y + wd.z * xd.z + wd.w * xd.w;
    }
    float acc = (a0 + a1) + (a2 + a3);
    #pragma unroll
    for (int o = 16; o; o >>= 1) acc += __shfl_down_sync(0xFFFFFFFFu, acc, o);
    return acc;
}

// smem-slot warp dot over 1024 floats
__device__ __forceinline__ float dot_s(const float* w, const float* x, int lane) {
    const float4* w4 = (const float4*)w;
    const float4* x4 = (const float4*)x;
    float a0 = 0.f, a1 = 0.f, a2 = 0.f, a3 = 0.f;
    #pragma unroll
    for (int u = 0; u < 8; u += 4) {
        float4 wa = w4[lane + 32 * u];       float4 xa = x4[lane + 32 * u];
        float4 wb = w4[lane + 32 * (u + 1)]; float4 xb = x4[lane + 32 * (u + 1)];
        float4 wc = w4[lane + 32 * (u + 2)]; float4 xc = x4[lane + 32 * (u + 2)];
        float4 wd = w4[lane + 32 * (u + 3)]; float4 xd = x4[lane + 32 * (u + 3)];
        a0 += wa.x * xa.x + wa.y * xa.y + wa.z * xa.z + wa.w * xa.w;
        a1 += wb.x * xb.x + wb.y * xb.y + wb.z * xb.z + wb.w * xb.w;
        a2 += wc.x * xc.x + wc.y * xc.y + wc.z * xc.z + wc.w * xc.w;
        a3 += wd.x * xd.x + wd.y * xd.y + wd.z * xd.z + wd.w * xd.w;
    }
    float acc = (a0 + a1) + (a2 + a3);
    #pragma unroll
    for (int o = 16; o; o >>= 1) acc += __shfl_down_sync(0xFFFFFFFFu, acc, o);
    return acc;
}

// ---- mbarrier / bulk-copy primitives ----
__device__ __forceinline__ void mb_init(uint32_t a, uint32_t cnt) {
    asm volatile("mbarrier.init.shared.b64 [%0], %1;" :: "r"(a), "r"(cnt) : "memory");
}
__device__ __forceinline__ void mb_expect(uint32_t a, uint32_t tx) {
    asm volatile("mbarrier.arrive.expect_tx.shared.b64 _, [%0], %1;" :: "r"(a), "r"(tx) : "memory");
}
__device__ __forceinline__ void mb_wait(uint32_t a, uint32_t parity) {
    uint32_t done;
    asm volatile(
        "{\n\t.reg .pred p;\n\t"
        "mbarrier.try_wait.parity.acquire.cta.shared::cta.b64 p, [%1], %2;\n\t"
        "selp.b32 %0, 1, 0, p;\n\t}"
        : "=r"(done) : "r"(a), "r"(parity) : "memory");
    if (!done) {
        asm volatile(
            "{\n\t.reg .pred P1;\n\t"
            "WAIT_LOOP_%=:\n\t"
            "mbarrier.try_wait.parity.acquire.cta.shared::cta.b64 P1, [%0], %1, 0x989680;\n\t"
            "@P1 bra.uni WAIT_DONE_%=;\n\t"
            "bra.uni WAIT_LOOP_%=;\n\t"
            "WAIT_DONE_%=:\n\t}"
            :: "r"(a), "r"(parity) : "memory");
    }
}
__device__ __forceinline__ void bulk_ld(uint32_t dst, const float* src, uint32_t bytes, uint32_t mbar) {
    asm volatile(
        "cp.async.bulk.shared::cluster.global.mbarrier::complete_tx::bytes [%0], [%1], %2, [%3];"
        :: "r"(dst), "l"(src), "r"(bytes), "r"(mbar) : "memory");
}

// ---- stage geometry: every task is one 4KB row ----
__device__ __forceinline__ int stageNT(int stg) {
    switch (stg) {
        case 0: return 3 * E;
        case 1: return E;
        case 2: return HH + E;
        case 3: return 4 * E;
        default: return NV;
    }
}
__device__ __forceinline__ const float* srcptr(const P& p, int stg, int l, int vr) {
    switch (stg) {
        case 0: { int m = vr >> 10;
                  const float* W = (m == 0 ? p.kw : (m == 1 ? p.vw : p.rw)) + (size_t)l * E * E;
                  return W + (size_t)(vr & 1023) * E; }
        case 1: return p.ow + (size_t)l * E * E + (size_t)vr * E;
        case 2: return (vr < 4096) ? p.fkw + (size_t)l * HH * E + (size_t)vr * E
                                   : p.frw + (size_t)l * E * E + (size_t)(vr - 4096) * E;
        case 3: return p.fvw + (size_t)l * E * HH + (size_t)vr * E;
        default: return p.head + (size_t)vr * E;
    }
}
__device__ __forceinline__ int xoff(int stg, int vr) {
    switch (stg) {
        case 0: return (vr >> 10) << 10;
        case 2: return (vr < 4096) ? 0 : E;
        case 3: return (vr & 3) << 10;
        default: return 0;
    }
}
__device__ __forceinline__ float* outp(const P& p, int stg, int vr) {
    switch (stg) {
        case 0: return g_kvr + vr;
        case 1: return g_ow + vr;
        case 2: return (vr < 4096) ? g_fk + vr : g_fr + (vr - 4096);
        case 3: return g_fvd + vr;
        default: return p.out + vr;
    }
}
// block-contiguous range + TMA quota q = min(32, n/2)
__device__ __forceinline__ void stage_range(int stg, int nb, int b, int& rs, int& n, int& q) {
    int NT = stageNT(stg);
    rs = (int)(((long long)NT * b) / nb);
    int re = (int)(((long long)NT * (b + 1)) / nb);
    n = re - rs;
    q = n >> 1;
    if (q > WPB) q = WPB;
}

// issue this warp's TMA row for stage (stg,l) -- called ONE STAGE EARLY
__device__ __forceinline__ void tma_issue_stage(const P& p, int stg, int l,
                                                uint32_t slot_u32, uint32_t mybar,
                                                int lane, int warp) {
    int rs, n, qn;
    stage_range(stg, p.nb, blockIdx.x, rs, n, qn);
    if (warp < qn && lane == 0) {
        mb_expect(mybar, 4096u);
        bulk_ld(slot_u32, srcptr(p, stg, l, rs + warp), 4096u, mybar);
    }
}

// run a stage: LDG rows [rs+q, rs+n) strided over 32 warps, then consume own TMA row
__device__ __forceinline__ void stage_run(const P& p, int stg, int l, float* sop,
                                          float* slot, int& phm,
                                          int lane, int warp) {
    int rs, n, q;
    stage_range(stg, p.nb, blockIdx.x, rs, n, q);
    for (int t = rs + q + warp; t < rs + n; t += WPB) {
        float acc = dot_g(srcptr(p, stg, l, t), sop + xoff(stg, t), lane);
        if (lane == 0) *outp(p, stg, t) = acc;
    }
    if (warp < q) {
        // own TMA row rs+warp (issued a stage ago; should be resident)
        uint32_t mybar_local;
        asm("{ .reg .u64 t; cvta.to.shared.u64 t, %1; cvt.u32.u64 %0, t; }"
            : "=r"(mybar_local) : "l"((void*)(slot + E)));  // mbar stored right after slot
        mb_wait(mybar_local, (uint32_t)phm);
        phm ^= 1;
        int vr = rs + warp;
        float acc = dot_s(slot, sop + xoff(stg, vr), lane);
        if (lane == 0) *outp(p, stg, vr) = acc;
        __syncwarp();
    }
}

// ---- param staging (single buffer) ----
__device__ __forceinline__ void cpa16(float* smem_dst, const float* g) {
    unsigned saddr = (unsigned)__cvta_generic_to_shared(smem_dst);
    asm volatile("cp.async.cg.shared.global [%0], [%1], 16;" :: "r"(saddr), "l"(g));
}
__device__ __forceinline__ const float* par_src(const P& p, int l, int a) {
    const float* st = p.state + (size_t)l * 5 * E;
    switch (a) {
        case 0:  return p.ln1w + l * E;
        case 1:  return p.ln1b + l * E;
        case 2:  return p.tmk + l * E;
        case 3:  return p.tmv + l * E;
        case 4:  return p.tmr + l * E;
        case 5:  return st + E;
        case 6:  return p.tf + l * E;
        case 7:  return p.td + l * E;
        case 8:  return st + 2 * E;
        case 9:  return st + 3 * E;
        case 10: return st + 4 * E;
        case 11: return p.ln2w + l * E;
        case 12: return p.ln2b + l * E;
        case 13: return p.ftmk + l * E;
        case 14: return p.ftmr + l * E;
        default: return st;
    }
}
__device__ __forceinline__ void prefetch_layer(const P& p, int l1, float* dst) {
    if (l1 < NL) {
        for (int t = threadIdx.x; t < NPAR * 256; t += T) {
            int a = t >> 8, i = (t & 255) << 2;
            cpa16(dst + a * E + i, par_src(p, l1, a) + i);
        }
    } else if (l1 == NL) {
        for (int t = threadIdx.x; t < 512; t += T) {
            int a = t >> 8, i = (t & 255) << 2;
            cpa16(dst + a * E + i, (a ? p.lnoutb : p.lnoutw) + i);
        }
    }
    asm volatile("cp.async.commit_group;" ::: "memory");
}
#define CP_WAIT() asm volatile("cp.async.wait_group 0;" ::: "memory")

// per-warp region: slot[E floats] + mbar(8B) + pad -> stride E + 4 floats
#define WSLOT (E + 4)
// smem: sx[E] + sop[HH] + par[NPAR*E] + warpregions[WPB*WSLOT]
#define SMEM_FLOATS (E + HH + NPAR * E + WPB * WSLOT)

__global__ void __launch_bounds__(T, 1) rwkv_kernel(P p) {
    extern __shared__ float smem[];
    float* sx    = smem;                         // [E]
    float* sop   = smem + E;                     // [HH]
    float* par   = smem + E + HH;                // [NPAR*E]
    float* wreg  = smem + E + HH + NPAR * E;     // [WPB*WSLOT]
    __shared__ float sred[2 * WPB + 2];

    const int tid = threadIdx.x, lane = tid & 31, warp = tid >> 5;
    const bool w0 = (p.ws && blockIdx.x == 0);
    float* outS = p.out + NV;

    float* slot = wreg + warp * WSLOT;           // 4KB slot; mbar at slot+E
    uint32_t slot_u32, mybar;
    asm("{ .reg .u64 t; cvta.to.shared.u64 t, %1; cvt.u32.u64 %0, t; }"
        : "=r"(slot_u32) : "l"((void*)slot));
    asm("{ .reg .u64 t; cvta.to.shared.u64 t, %1; cvt.u32.u64 %0, t; }"
        : "=r"(mybar) : "l"((void*)(slot + E)));
    if (lane == 0) mb_init(mybar, 1);
    __syncthreads();
    int phm = 0;

    prefetch_layer(p, 0, par);
    tma_issue_stage(p, 0, 0, slot_u32, mybar, lane, warp);   // layer-0 kvr TMA rows

    float s = 0.f, s2 = 0.f;
    for (int i = tid; i < E; i += T) { float v = __ldg(p.ctx + i); sx[i] = v; s += v; s2 += v * v; }
    block_reduce2(s, s2, sred);
    {
        float mu = s * (1.f / E);
        float rs_ = rsqrtf(s2 * (1.f / E) - mu * mu + 1e-5f);
        for (int i = tid; i < E; i += T)
            sx[i] = (sx[i] - mu) * rs_ * __ldg(p.ln0w + i) + __ldg(p.ln0b + i);
    }
    CP_WAIT();
    __syncthreads();

    for (int l = 0; l < NL; l++) {
        // ======== Stage A: combine prev FFN + LN1 + time-mix; kvr GEMV ========
        if (l > 0) {
            for (int i = tid; i < E; i += T) {
                float4 fv4 = *(const float4*)(g_fvd + 4 * i);
                float fr = 1.f / (1.f + __expf(-g_fr[i]));
                sx[i] += fr * ((fv4.x + fv4.y) + (fv4.z + fv4.w));
            }
        }
        s = 0.f; s2 = 0.f;
        for (int i = tid; i < E; i += T) { float v = sx[i]; s += v; s2 += v * v; }
        block_reduce2(s, s2, sred);
        {
            float mu = s * (1.f / E);
            float rs_ = rsqrtf(s2 * (1.f / E) - mu * mu + 1e-5f);
            for (int i = tid; i < E; i += T) {
                float xn = (sx[i] - mu) * rs_ * par[0 * E + i] + par[1 * E + i];
                float spv = par[5 * E + i];
                float a = par[2 * E + i], b = par[3 * E + i], c = par[4 * E + i];
                sop[i]         = xn * a + spv * (1.f - a);
                sop[E + i]     = xn * b + spv * (1.f - b);
                sop[2 * E + i] = xn * c + spv * (1.f - c);
                if (w0) outS[(size_t)(5 * l + 1) * E + i] = xn;
            }
        }
        __syncthreads();
        stage_run(p, 0, l, sop, slot, phm, lane, warp);
        tma_issue_stage(p, 1, l, slot_u32, mybar, lane, warp);
        grid_sync(p.nb);

        // ======== Stage B: WKV; ow GEMV ========
        for (int i = tid; i < E; i += T) {
            float k  = g_kvr[i];
            float v  = g_kvr[E + i];
            float rr = g_kvr[2 * E + i];
            float A = par[8 * E + i], B = par[9 * E + i], Pp = par[10 * E + i];
            float ww = par[6 * E + i] + k;
            float qq = fmaxf(Pp, ww);
            float e1 = __expf(Pp - qq), e2 = __expf(ww - qq);
            float num = e1 * A + e2 * v, den = e1 * B + e2;
            float r = 1.f / (1.f + __expf(-rr));
            sop[i] = r * num / den;
            if (w0) {
                float ww2 = Pp + par[7 * E + i];
                float p2 = fmaxf(ww2, k);
                float e1b = __expf(ww2 - p2), e2b = __expf(k - p2);
                outS[(size_t)(5 * l + 2) * E + i] = e1b * A + e2b * v;
                outS[(size_t)(5 * l + 3) * E + i] = e1b * B + e2b;
                outS[(size_t)(5 * l + 4) * E + i] = p2;
            }
        }
        __syncthreads();
        stage_run(p, 1, l, sop, slot, phm, lane, warp);
        tma_issue_stage(p, 2, l, slot_u32, mybar, lane, warp);
        grid_sync(p.nb);

        // ======== Stage C: x += ow; LN2 + chan-mix; fk+fr GEMV ========
        for (int i = tid; i < E; i += T) sx[i] += g_ow[i];
        s = 0.f; s2 = 0.f;
        for (int i = tid; i < E; i += T) { float v = sx[i]; s += v; s2 += v * v; }
        block_reduce2(s, s2, sred);
        {
            float mu = s * (1.f / E);
            float rs_ = rsqrtf(s2 * (1.f / E) - mu * mu + 1e-5f);
            for (int i = tid; i < E; i += T) {
                float xn2 = (sx[i] - mu) * rs_ * par[11 * E + i] + par[12 * E + i];
                float sv = par[15 * E + i];
                float a = par[13 * E + i], b = par[14 * E + i];
                sop[i]     = xn2 * a + sv * (1.f - a);
                sop[E + i] = xn2 * b + sv * (1.f - b);
                if (w0) outS[(size_t)(5 * l + 0) * E + i] = xn2;
            }
        }
        __syncthreads();
        prefetch_layer(p, l + 1, par);   // params' last use was just above
        stage_run(p, 2, l, sop, slot, phm, lane, warp);
        tma_issue_stage(p, 3, l, slot_u32, mybar, lane, warp);
        grid_sync(p.nb);

        // ======== Stage D: kk = relu^2(fk); fv GEMV ========
        for (int i = tid; i < HH; i += T) {
            float a = fmaxf(g_fk[i], 0.f);
            sop[i] = a * a;
        }
        __syncthreads();
        stage_run(p, 3, l, sop, slot, phm, lane, warp);
        if (l + 1 < NL) tma_issue_stage(p, 0, l + 1, slot_u32, mybar, lane, warp);
        else            tma_issue_stage(p, 4, 0, slot_u32, mybar, lane, warp);
        grid_sync(p.nb);
        CP_WAIT();
    }

    // ======== final: combine last FFN, LN_out, head GEMV ========
    for (int i = tid; i < E; i += T) {
        float4 fv4 = *(const float4*)(g_fvd + 4 * i);
        float fr = 1.f / (1.f + __expf(-g_fr[i]));
        sx[i] += fr * ((fv4.x + fv4.y) + (fv4.z + fv4.w));
    }
    s = 0.f; s2 = 0.f;
    for (int i = tid; i < E; i += T) { float v = sx[i]; s += v; s2 += v * v; }
    block_reduce2(s, s2, sred);
    {
        float mu = s * (1.f / E);
        float rs_ = rsqrtf(s2 * (1.f / E) - mu * mu + 1e-5f);
        for (int i = tid; i < E; i += T)
            sop[i] = (sx[i] - mu) * rs_ * par[i] + par[E + i];
    }
    __syncthreads();
    stage_run(p, 4, 0, sop, slot, phm, lane, warp);    // -> logits
}

extern "C" void kernel_launch(void* const* d_in, const int* in_sizes, int n_in,
                              void* d_out, int out_size) {
    (void)in_sizes; (void)n_in;
    P p;
    p.ctx    = (const float*)d_in[0];
    p.state  = (const float*)d_in[1];
    p.ln0w   = (const float*)d_in[2];
    p.ln0b   = (const float*)d_in[3];
    p.ln1w   = (const float*)d_in[4];
    p.ln1b   = (const float*)d_in[5];
    p.ln2w   = (const float*)d_in[6];
    p.ln2b   = (const float*)d_in[7];
    p.td     = (const float*)d_in[8];
    p.tf     = (const float*)d_in[9];
    p.tmk    = (const float*)d_in[10];
    p.tmv    = (const float*)d_in[11];
    p.tmr    = (const float*)d_in[12];
    p.kw     = (const float*)d_in[13];
    p.vw     = (const float*)d_in[14];
    p.rw     = (const float*)d_in[15];
    p.ow     = (const float*)d_in[16];
    p.ftmk   = (const float*)d_in[17];
    p.ftmr   = (const float*)d_in[18];
    p.fkw    = (const float*)d_in[19];
    p.frw    = (const float*)d_in[20];
    p.fvw    = (const float*)d_in[21];
    p.lnoutw = (const float*)d_in[22];
    p.lnoutb = (const float*)d_in[23];
    p.head   = (const float*)d_in[24];
    p.out    = (float*)d_out;

    int dev = 0;
    cudaGetDevice(&dev);
    int nsm = 0;
    cudaDeviceGetAttribute(&nsm, cudaDevAttrMultiProcessorCount, dev);
    if (nsm <= 0) nsm = 148;
    if (nsm > 256) nsm = 256;
    p.nb = nsm;
    p.ws = (out_size >= NV + 5 * NL * E) ? 1 : 0;

    cudaFuncSetAttribute(rwkv_kernel, cudaFuncAttributeMaxDynamicSharedMemorySize,
                         SMEM_FLOATS * sizeof(float));

    void* baddr = nullptr;
    cudaGetSymbolAddress(&baddr, g_bar);
    cudaMemsetAsync(baddr, 0, sizeof(unsigned int) * 2, 0);

    rwkv_kernel<<<nsm, T, SMEM_FLOATS * sizeof(float)>>>(p);
}

// round 13
// speedup vs baseline: 1.4518x; 1.4015x over previous
#include <cuda_runtime.h>

// RWKV v4 single-token forward, persistent kernel, round 13.
// EXACT R5 (best, 620us) + ONE isolated change: the head GEMV processes two
// rows per iteration with interleaved loads (2x per-warp loads in flight).
// Purpose: cleanly measure whether per-warp MLP limits the ~2.4TB/s streaming
// plateau. All TMA paths abandoned after 5 consecutive regressions (R8-R12).

#define E    1024
#define HH   4096
#define NL   24
#define NV   50277
#define T    1024
#define WPB  32
#define NPAR 16

// ---- persistent device scratch ----
__device__ float g_kvr[3 * E];     // k, v, r (whole rows, no partials)
__device__ float g_op[2][E];       // ow half-row partials
__device__ float g_fk[HH];         // ffn_k pre-relu (whole rows)
__device__ float g_frp[2][E];      // ffn_r half-row partials
__device__ float g_fvp[4][E];      // ffn_v quarter-row partials
__device__ unsigned int g_bar[2];  // {count, generation}; memset per launch

struct P {
    const float *ctx, *state, *ln0w, *ln0b, *ln1w, *ln1b, *ln2w, *ln2b;
    const float *td, *tf, *tmk, *tmv, *tmr, *kw, *vw, *rw, *ow;
    const float *ftmk, *ftmr, *fkw, *frw, *fvw, *lnoutw, *lnoutb, *head;
    float* out;
    int nb;
    int ws;
};

__device__ __forceinline__ void grid_sync(int nb) {
    __syncthreads();
    if (threadIdx.x == 0) {
        unsigned int gen = ((volatile unsigned int*)g_bar)[1];
        __threadfence();
        if (atomicAdd(&g_bar[0], 1u) == (unsigned int)(nb - 1)) {
            atomicExch(&g_bar[0], 0u);
            __threadfence();
            atomicAdd(&g_bar[1], 1u);
        } else {
            while (((volatile unsigned int*)g_bar)[1] == gen) { __nanosleep(64); }
        }
        __threadfence();
    }
    __syncthreads();
}

__device__ __forceinline__ void block_reduce2(float& a, float& b, float* sr) {
    #pragma unroll
    for (int o = 16; o; o >>= 1) {
        a += __shfl_down_sync(0xFFFFFFFFu, a, o);
        b += __shfl_down_sync(0xFFFFFFFFu, b, o);
    }
    int w = threadIdx.x >> 5, l = threadIdx.x & 31;
    __syncthreads();
    if (l == 0) { sr[w] = a; sr[w + WPB] = b; }
    __syncthreads();
    if (threadIdx.x == 0) {
        float sa = 0.f, sb2 = 0.f;
        #pragma unroll
        for (int i = 0; i < WPB; i++) { sa += sr[i]; sb2 += sr[i + WPB]; }
        sr[2 * WPB] = sa; sr[2 * WPB + 1] = sb2;
    }
    __syncthreads();
    a = sr[2 * WPB];
    b = sr[2 * WPB + 1];
}

// warp dot over 128*N4 floats; weights streamed with .cs (read-once)
template <int N4>
__device__ __forceinline__ float warp_dot(const float* __restrict__ w,
                                          const float* x, int lane) {
    const float4* __restrict__ w4 = (const float4*)w;
    const float4* x4 = (const float4*)x;
    float a0 = 0.f, a1 = 0.f, a2 = 0.f, a3 = 0.f;
    #pragma unroll
    for (int u = 0; u < N4; u += 4) {
        float4 wa = __ldcs(&w4[lane + 32 * u]);
        float4 xa = x4[lane + 32 * u];
        a0 += wa.x * xa.x + wa.y * xa.y + wa.z * xa.z + wa.w * xa.w;
        if (u + 1 < N4) {
            float4 wb = __ldcs(&w4[lane + 32 * (u + 1)]);
            float4 xb = x4[lane + 32 * (u + 1)];
            a1 += wb.x * xb.x + wb.y * xb.y + wb.z * xb.z + wb.w * xb.w;
        }
        if (u + 2 < N4) {
            float4 wc = __ldcs(&w4[lane + 32 * (u + 2)]);
            float4 xc = x4[lane + 32 * (u + 2)];
            a2 += wc.x * xc.x + wc.y * xc.y + wc.z * xc.z + wc.w * xc.w;
        }
        if (u + 3 < N4) {
            float4 wd = __ldcs(&w4[lane + 32 * (u + 3)]);
            float4 xd = x4[lane + 32 * (u + 3)];
            a3 += wd.x * xd.x + wd.y * xd.y + wd.z * xd.z + wd.w * xd.w;
        }
    }
    float acc = (a0 + a1) + (a2 + a3);
    #pragma unroll
    for (int o = 16; o; o >>= 1) acc += __shfl_down_sync(0xFFFFFFFFu, acc, o);
    return acc;
}

// two-row interleaved dot (head): 2x in-flight weight loads per warp
__device__ __forceinline__ void warp_dot2(const float* __restrict__ w0,
                                          const float* __restrict__ w1,
                                          const float* x, int lane,
                                          float& o0, float& o1) {
    const float4* __restrict__ a4 = (const float4*)w0;
    const float4* __restrict__ b4 = (const float4*)w1;
    const float4* x4 = (const float4*)x;
    float p0 = 0.f, p1 = 0.f, q0 = 0.f, q1 = 0.f;
    #pragma unroll
    for (int u = 0; u < 8; u += 2) {
        float4 xa = x4[lane + 32 * u];
        float4 xb = x4[lane + 32 * (u + 1)];
        float4 wa = __ldcs(&a4[lane + 32 * u]);
        float4 wb = __ldcs(&a4[lane + 32 * (u + 1)]);
        float4 va = __ldcs(&b4[lane + 32 * u]);
        float4 vb = __ldcs(&b4[lane + 32 * (u + 1)]);
        p0 += wa.x * xa.x + wa.y * xa.y + wa.z * xa.z + wa.w * xa.w;
        p1 += wb.x * xb.x + wb.y * xb.y + wb.z * xb.z + wb.w * xb.w;
        q0 += va.x * xa.x + va.y * xa.y + va.z * xa.z + va.w * xa.w;
        q1 += vb.x * xb.x + vb.y * xb.y + vb.z * xb.z + vb.w * xb.w;
    }
    float r0 = p0 + p1, r1 = q0 + q1;
    #pragma unroll
    for (int o = 16; o; o >>= 1) {
        r0 += __shfl_down_sync(0xFFFFFFFFu, r0, o);
        r1 += __shfl_down_sync(0xFFFFFFFFu, r1, o);
    }
    o0 = r0; o1 = r1;
}

__device__ __forceinline__ void cpa16(float* smem_dst, const float* g) {
    unsigned saddr = (unsigned)__cvta_generic_to_shared(smem_dst);
    asm volatile("cp.async.cg.shared.global [%0], [%1], 16;" :: "r"(saddr), "l"(g));
}

__device__ __forceinline__ const float* par_src(const P& p, int l, int a) {
    const float* st = p.state + (size_t)l * 5 * E;
    switch (a) {
        case 0:  return p.ln1w + l * E;
        case 1:  return p.ln1b + l * E;
        case 2:  return p.tmk + l * E;
        case 3:  return p.tmv + l * E;
        case 4:  return p.tmr + l * E;
        case 5:  return st + E;
        case 6:  return p.tf + l * E;
        case 7:  return p.td + l * E;
        case 8:  return st + 2 * E;
        case 9:  return st + 3 * E;
        case 10: return st + 4 * E;
        case 11: return p.ln2w + l * E;
        case 12: return p.ln2b + l * E;
        case 13: return p.ftmk + l * E;
        case 14: return p.ftmr + l * E;
        default: return st;
    }
}

__device__ __forceinline__ void prefetch_layer(const P& p, int l1, float* dst) {
    if (l1 < NL) {
        for (int t = threadIdx.x; t < NPAR * 256; t += T) {
            int a = t >> 8, i = (t & 255) << 2;
            cpa16(dst + a * E + i, par_src(p, l1, a) + i);
        }
    } else if (l1 == NL) {
        for (int t = threadIdx.x; t < 512; t += T) {
            int a = t >> 8, i = (t & 255) << 2;
            cpa16(dst + a * E + i, (a ? p.lnoutb : p.lnoutw) + i);
        }
    }
    asm volatile("cp.async.commit_group;" ::: "memory");
}

#define CP_WAIT() asm volatile("cp.async.wait_group 0;" ::: "memory")

#define SMEM_FLOATS (E + HH + 128 + 2 * NPAR * E)

__global__ void __launch_bounds__(T, 1) rwkv_kernel(P p) {
    extern __shared__ float smem[];
    float* sx   = smem;
    float* sop  = smem + E;
    float* sred = smem + E + HH;
    float* par0 = smem + E + HH + 128;

    const int tid = threadIdx.x, lane = tid & 31, warp = tid >> 5;
    const int gw = blockIdx.x * WPB + warp;
    const int NW = p.nb * WPB;
    const bool w0 = (p.ws && blockIdx.x == 0);
    float* outS = p.out + NV;
    int buf = 0;

    prefetch_layer(p, 0, par0);

    float s = 0.f, s2 = 0.f;
    for (int i = tid; i < E; i += T) { float v = p.ctx[i]; sop[i] = v; s += v; s2 += v * v; }
    block_reduce2(s, s2, sred);
    {
        float mu = s * (1.f / E);
        float rs = rsqrtf(s2 * (1.f / E) - mu * mu + 1e-5f);
        for (int i = tid; i < E; i += T)
            sx[i] = (sop[i] - mu) * rs * p.ln0w[i] + p.ln0b[i];
    }
    CP_WAIT();
    __syncthreads();

    for (int l = 0; l < NL; l++) {
        const float* pr = par0 + buf * NPAR * E;

        // ======== Stage A: combine prev FFN + LN1 + time-mix + k/v/r GEMV ========
        if (l > 0) {
            for (int i = tid; i < E; i += T) {
                float fr = 1.f / (1.f + __expf(-(g_frp[0][i] + g_frp[1][i])));
                sx[i] += fr * (g_fvp[0][i] + g_fvp[1][i] + g_fvp[2][i] + g_fvp[3][i]);
            }
        }
        s = 0.f; s2 = 0.f;
        for (int i = tid; i < E; i += T) { float v = sx[i]; s += v; s2 += v * v; }
        block_reduce2(s, s2, sred);
        {
            float mu = s * (1.f / E);
            float rs = rsqrtf(s2 * (1.f / E) - mu * mu + 1e-5f);
            for (int i = tid; i < E; i += T) {
                float xn = (sx[i] - mu) * rs * pr[0 * E + i] + pr[1 * E + i];
                float spv = pr[5 * E + i];
                float a = pr[2 * E + i], b = pr[3 * E + i], c = pr[4 * E + i];
                sop[i]         = xn * a + spv * (1.f - a);
                sop[E + i]     = xn * b + spv * (1.f - b);
                sop[2 * E + i] = xn * c + spv * (1.f - c);
                if (w0) outS[(size_t)(5 * l + 1) * E + i] = xn;
            }
        }
        __syncthreads();
        prefetch_layer(p, l + 1, par0 + (buf ^ 1) * NPAR * E);
        if (gw < 3072) {
            int m = gw >> 10, i = gw & 1023;
            const float* W = (m == 0 ? p.kw : (m == 1 ? p.vw : p.rw)) + (size_t)l * E * E;
            float acc = warp_dot<8>(W + (size_t)i * E, sop + (m << 10), lane);
            if (lane == 0) g_kvr[gw] = acc;
        }
        grid_sync(p.nb);

        // ======== Stage B: WKV + ow GEMV (half rows) ========
        {
            for (int i = tid; i < E; i += T) {
                float k  = g_kvr[i];
                float v  = g_kvr[E + i];
                float rr = g_kvr[2 * E + i];
                float A = pr[8 * E + i], B = pr[9 * E + i], Pp = pr[10 * E + i];
                float ww = pr[6 * E + i] + k;
                float q = fmaxf(Pp, ww);
                float e1 = __expf(Pp - q), e2 = __expf(ww - q);
                float num = e1 * A + e2 * v, den = e1 * B + e2;
                float r = 1.f / (1.f + __expf(-rr));
                sop[i] = r * num / den;
                if (w0) {
                    float ww2 = Pp + pr[7 * E + i];
                    float p2 = fmaxf(ww2, k);
                    float e1b = __expf(ww2 - p2), e2b = __expf(k - p2);
                    outS[(size_t)(5 * l + 2) * E + i] = e1b * A + e2b * v;
                    outS[(size_t)(5 * l + 3) * E + i] = e1b * B + e2b;
                    outS[(size_t)(5 * l + 4) * E + i] = p2;
                }
            }
        }
        __syncthreads();
        if (gw < 2048) {
            int h = gw & 1, i = gw >> 1;
            const float* OW = p.ow + (size_t)l * E * E;
            float acc = warp_dot<4>(OW + (size_t)i * E + h * 512, sop + h * 512, lane);
            if (lane == 0) g_op[h][i] = acc;
        }
        grid_sync(p.nb);

        // ======== Stage C: x += ow; LN2 + chan-mix + fk (whole) / fr (half) ========
        for (int i = tid; i < E; i += T) sx[i] += g_op[0][i] + g_op[1][i];
        s = 0.f; s2 = 0.f;
        for (int i = tid; i < E; i += T) { float v = sx[i]; s += v; s2 += v * v; }
        block_reduce2(s, s2, sred);
        {
            float mu = s * (1.f / E);
            float rs = rsqrtf(s2 * (1.f / E) - mu * mu + 1e-5f);
            for (int i = tid; i < E; i += T) {
                float xn2 = (sx[i] - mu) * rs * pr[11 * E + i] + pr[12 * E + i];
                float sv = pr[15 * E + i];
                float a = pr[13 * E + i], b = pr[14 * E + i];
                sop[i]     = xn2 * a + sv * (1.f - a);
                sop[E + i] = xn2 * b + sv * (1.f - b);
                if (w0) outS[(size_t)(5 * l + 0) * E + i] = xn2;
            }
        }
        __syncthreads();
        {
            const float* FK = p.fkw + (size_t)l * HH * E;
            const float* FR = p.frw + (size_t)l * E * E;
            if (gw < 4096) {
                float acc = warp_dot<8>(FK + (size_t)gw * E, sop, lane);
                if (lane == 0) g_fk[gw] = acc;
            }
            // fr halves: 2048 tasks on warps [4096,4864) and [0,1280)
            int ft = (gw >= 4096) ? (gw - 4096) : (gw < 1280 ? 768 + gw : -1);
            if (ft >= 0 && ft < 2048) {
                int i = ft >> 1, h = ft & 1;
                float acc = warp_dot<4>(FR + (size_t)i * E + h * 512, sop + E + h * 512, lane);
                if (lane == 0) g_frp[h][i] = acc;
            }
        }
        grid_sync(p.nb);

        // ======== Stage D: kk = relu^2(fk); fv GEMV (quarter rows) ========
        for (int i = tid; i < HH; i += T) {
            float a = fmaxf(g_fk[i], 0.f);
            sop[i] = a * a;
        }
        __syncthreads();
        if (gw < 4096) {
            int c = gw & 3, i = gw >> 2;
            const float* FV = p.fvw + (size_t)l * E * HH;
            float acc = warp_dot<8>(FV + (size_t)i * HH + c * E, sop + c * E, lane);
            if (lane == 0) g_fvp[c][i] = acc;
        }
        grid_sync(p.nb);

        CP_WAIT();
        buf ^= 1;
    }

    // ======== final: combine last FFN, LN_out, head GEMV (2-row interleaved) ========
    const float* pr = par0 + buf * NPAR * E;
    for (int i = tid; i < E; i += T) {
        float fr = 1.f / (1.f + __expf(-(g_frp[0][i] + g_frp[1][i])));
        sx[i] += fr * (g_fvp[0][i] + g_fvp[1][i] + g_fvp[2][i] + g_fvp[3][i]);
    }
    s = 0.f; s2 = 0.f;
    for (int i = tid; i < E; i += T) { float v = sx[i]; s += v; s2 += v * v; }
    block_reduce2(s, s2, sred);
    {
        float mu = s * (1.f / E);
        float rs = rsqrtf(s2 * (1.f / E) - mu * mu + 1e-5f);
        for (int i = tid; i < E; i += T)
            sop[i] = (sx[i] - mu) * rs * pr[i] + pr[E + i];
    }
    __syncthreads();
    for (int t = gw; t < NV; t += 2 * NW) {
        int t2 = t + NW;
        const float* w0p = p.head + (size_t)t * E;
        const float* w1p = p.head + (size_t)(t2 < NV ? t2 : t) * E;
        float r0, r1;
        warp_dot2(w0p, w1p, sop, lane, r0, r1);
        if (lane == 0) {
            p.out[t] = r0;
            if (t2 < NV) p.out[t2] = r1;
        }
    }
}

extern "C" void kernel_launch(void* const* d_in, const int* in_sizes, int n_in,
                              void* d_out, int out_size) {
    (void)in_sizes; (void)n_in;
    P p;
    p.ctx    = (const float*)d_in[0];
    p.state  = (const float*)d_in[1];
    p.ln0w   = (const float*)d_in[2];
    p.ln0b   = (const float*)d_in[3];
    p.ln1w   = (const float*)d_in[4];
    p.ln1b   = (const float*)d_in[5];
    p.ln2w   = (const float*)d_in[6];
    p.ln2b   = (const float*)d_in[7];
    p.td     = (const float*)d_in[8];
    p.tf     = (const float*)d_in[9];
    p.tmk    = (const float*)d_in[10];
    p.tmv    = (const float*)d_in[11];
    p.tmr    = (const float*)d_in[12];
    p.kw     = (const float*)d_in[13];
    p.vw     = (const float*)d_in[14];
    p.rw     = (const float*)d_in[15];
    p.ow     = (const float*)d_in[16];
    p.ftmk   = (const float*)d_in[17];
    p.ftmr   = (const float*)d_in[18];
    p.fkw    = (const float*)d_in[19];
    p.frw    = (const float*)d_in[20];
    p.fvw    = (const float*)d_in[21];
    p.lnoutw = (const float*)d_in[22];
    p.lnoutb = (const float*)d_in[23];
    p.head   = (const float*)d_in[24];
    p.out    = (float*)d_out;

    int dev = 0;
    cudaGetDevice(&dev);
    int nsm = 0;
    cudaDeviceGetAttribute(&nsm, cudaDevAttrMultiProcessorCount, dev);
    if (nsm <= 0) nsm = 148;
    if (nsm > 256) nsm = 256;
    p.nb = nsm;
    p.ws = (out_size >= NV + 5 * NL * E) ? 1 : 0;

    cudaFuncSetAttribute(rwkv_kernel, cudaFuncAttributeMaxDynamicSharedMemorySize,
                         SMEM_FLOATS * sizeof(float));

    void* baddr = nullptr;
    cudaGetSymbolAddress(&baddr, g_bar);
    cudaMemsetAsync(baddr, 0, sizeof(unsigned int) * 2, 0);

    rwkv_kernel<<<nsm, T, SMEM_FLOATS * sizeof(float)>>>(p);
}